// round 12
// baseline (speedup 1.0000x reference)
#include <cuda_runtime.h>
#include <cuda_bf16.h>
#include <cstdint>

// ---------------- problem constants ----------------
#define MAX_N 100000
#define MAX_E 1700000
#define F_IN  256
#define F_MID 128
#define F_OUT 64
#define NBLK  148          // <= SM count; 1 CTA/SM -> co-residency guaranteed
#define NTHR  1024
#define NWARPS (NBLK * 32) // 4736 warps chip-wide

// dynamic smem: GEMM1 phase needs W1(32768) + 2 dup-A buffers (2*32*264=16896)
// = 49664 floats = 198656 bytes (< 227KB cap)
#define SMEM_FLOATS 49664
#define SMEM_BYTES  (SMEM_FLOATS * 4)

// ---------------- device scratch (no allocations allowed) ----------------
__device__ int    g_deg[MAX_N];
__device__ float  g_dis[MAX_N];
__device__ int    g_rowptr[MAX_N + 1];
__device__ int    g_cursor[MAX_N];
__device__ int    g_bsum[128];
__device__ volatile unsigned g_bar_gen;   // monotonic, NEVER reset (replay-safe)
__device__ unsigned g_bar_cnt;
__device__ float2 g_cw[MAX_E];
__device__ float  g_XW1[(size_t)MAX_N * F_MID];
__device__ float  g_H[(size_t)MAX_N * F_MID];
__device__ float  g_HW2[(size_t)MAX_N * F_OUT];

// ---------------- packed f32x2 helpers (sm_103a) ----------------
__device__ __forceinline__ void ffma2(unsigned long long& d,
                                      unsigned long long a,
                                      unsigned long long b) {
    asm("fma.rn.f32x2 %0, %1, %2, %0;" : "+l"(d) : "l"(a), "l"(b));
}
__device__ __forceinline__ float2 unpack2(unsigned long long v) {
    float lo, hi;
    asm("mov.b64 {%0, %1}, %2;" : "=f"(lo), "=f"(hi) : "l"(v));
    return make_float2(lo, hi);
}

// ---------------- grid barrier (all NBLK blocks co-resident) ----------------
__device__ __forceinline__ void gbar() {
    __syncthreads();
    if (threadIdx.x == 0) {
        __threadfence();
        unsigned gen = g_bar_gen;                       // read BEFORE arrive
        if (atomicAdd(&g_bar_cnt, 1u) == NBLK - 1u) {
            g_bar_cnt = 0u;                             // reset BEFORE release
            __threadfence();
            g_bar_gen = gen + 1u;                       // release
        } else {
            while (g_bar_gen == gen) { }                // spin (volatile read)
        }
        __threadfence();
    }
    __syncthreads();
}

// ---------------- the whole GCN in one persistent kernel ----------------
__global__ __launch_bounds__(NTHR, 1)
void k_gcn(const float* __restrict__ X,  const float* __restrict__ W1,
           const float* __restrict__ W2, const int* __restrict__ erow,
           const int* __restrict__ ecol, int E, int n,
           float* __restrict__ out) {
    extern __shared__ float smp[];
    const int tid = threadIdx.x;
    const int bid = blockIdx.x;
    const int lane = tid & 31;
    const int wid  = tid >> 5;
    const int gstride = NBLK * NTHR;      // 151552

    // ---- phase A: zero degrees ----
    for (int i = bid * NTHR + tid; i < n; i += gstride) g_deg[i] = 0;
    gbar();

    // ---- phase B: degree histogram ----
    for (int e = bid * NTHR + tid; e < E; e += gstride)
        atomicAdd(&g_deg[erow[e]], 1);
    gbar();

    // ---- phase C: dis + block-local scan (blocks 0..97, 1024 rows each) ----
    int v = 0, incl = 0;
    const int i_scan = bid * NTHR + tid;
    if (bid < 98) {
        int* s = (int*)smp;
        v = (i_scan < n) ? g_deg[i_scan] : 0;
        if (i_scan < n) g_dis[i_scan] = rsqrtf((float)v);
        s[tid] = v;
        __syncthreads();
#pragma unroll
        for (int off = 1; off < NTHR; off <<= 1) {
            int t = (tid >= off) ? s[tid - off] : 0;
            __syncthreads();
            s[tid] += t;
            __syncthreads();
        }
        incl = s[tid];
        if (tid == NTHR - 1) g_bsum[bid] = incl;
    }
    gbar();

    // ---- phase D: block offset + rowptr/cursor ----
    if (bid < 98) {
        int* s2 = (int*)smp;
        if (tid < 128) s2[tid] = (tid < bid) ? g_bsum[tid] : 0;
        __syncthreads();
        if (tid < 64) s2[tid] += s2[tid + 64];
        __syncthreads();
        if (tid < 32) {
            int t = s2[tid] + s2[tid + 32];
#pragma unroll
            for (int off = 16; off > 0; off >>= 1)
                t += __shfl_down_sync(0xffffffffu, t, off);
            if (tid == 0) s2[0] = t;
        }
        __syncthreads();
        int excl = s2[0] + incl - v;
        if (i_scan < n) {
            g_rowptr[i_scan] = excl;
            g_cursor[i_scan] = excl;
            if (i_scan == n - 1) g_rowptr[n] = excl + v;
        }
    }
    gbar();

    // ---- phase E: scatter edges into CSR ----
    for (int e = bid * NTHR + tid; e < E; e += gstride) {
        int r = erow[e];
        int c = ecol[e];
        int p = atomicAdd(&g_cursor[r], 1);
        g_cw[p] = make_float2(__int_as_float(c), g_dis[r] * g_dis[c]);
    }
    gbar();

    // ---- phase F: GEMM1  g_XW1[n,128] = X[n,256] @ W1[256,128] ----
    // W1 smem-resident; A stored DUPLICATED (a,a) so the inner loop feeds
    // FFMA2 with 2x LDS.128 and zero packing movs.
    // BM=128, BK=32, TM=4, TN=4 (f32x2); 1024 threads.
    {
        float* Ws = smp;                 // [256][128] = 32768 floats
        float* As = smp + 32768;         // 2 x [32][264] dup layout
        const int tx = lane;             // *4 -> 128 cols
        const int ty = wid;              // *4 -> 128 rows
        const int ar = tid >> 3;         // A row this thread fills (0..127)
        const int akv = tid & 7;         // A k-vec (0..7)
        const int tiles = (n + 127) >> 7;

        // load all of W1 once (8192 float4, 8 per thread)
        for (int i = tid; i < 32768 / 4; i += NTHR)
            ((float4*)Ws)[i] = ((const float4*)W1)[i];

        for (int tile = bid; tile < tiles; tile += NBLK) {
            const int rowBase = tile << 7;
            const int gr_ld = rowBase + ar;
            unsigned long long acc2[4][2];
#pragma unroll
            for (int i = 0; i < 4; i++) { acc2[i][0] = 0ull; acc2[i][1] = 0ull; }

            // prologue: fill buf 0 with k0=0 (duplicated stores)
            float4 pa = make_float4(0.f, 0.f, 0.f, 0.f);
            if (gr_ld < n) pa = *(const float4*)&X[(size_t)gr_ld * F_IN + akv * 4];
            __syncthreads();    // protects prev tile's last-read buffer + W1 load
            {
                float* A0 = As;
                *(float2*)&A0[(akv * 4 + 0) * 264 + 2 * ar] = make_float2(pa.x, pa.x);
                *(float2*)&A0[(akv * 4 + 1) * 264 + 2 * ar] = make_float2(pa.y, pa.y);
                *(float2*)&A0[(akv * 4 + 2) * 264 + 2 * ar] = make_float2(pa.z, pa.z);
                *(float2*)&A0[(akv * 4 + 3) * 264 + 2 * ar] = make_float2(pa.w, pa.w);
            }
            __syncthreads();

            int buf = 0;
#pragma unroll
            for (int k0 = 0; k0 < F_IN; k0 += 32) {
                // prefetch next A fragment into registers
                if (k0 + 32 < F_IN && gr_ld < n)
                    pa = *(const float4*)&X[(size_t)gr_ld * F_IN + (k0 + 32) + akv * 4];
                const float* Ab = As + buf * 8448;
#pragma unroll
                for (int k = 0; k < 32; k++) {
                    const unsigned long long* Ad =
                        (const unsigned long long*)&Ab[k * 264 + ty * 8];
                    unsigned long long a0 = Ad[0], a1 = Ad[1];
                    unsigned long long a2 = Ad[2], a3 = Ad[3];
                    const unsigned long long* rb =
                        (const unsigned long long*)&Ws[(k0 + k) * 128 + tx * 4];
                    unsigned long long b01 = rb[0], b23 = rb[1];
                    ffma2(acc2[0][0], a0, b01); ffma2(acc2[0][1], a0, b23);
                    ffma2(acc2[1][0], a1, b01); ffma2(acc2[1][1], a1, b23);
                    ffma2(acc2[2][0], a2, b01); ffma2(acc2[2][1], a2, b23);
                    ffma2(acc2[3][0], a3, b01); ffma2(acc2[3][1], a3, b23);
                }
                if (k0 + 32 < F_IN) {
                    float* An = As + (buf ^ 1) * 8448;
                    An += (akv * 4) * 264 + 2 * ar;
                    *(float2*)&An[0]       = make_float2(pa.x, pa.x);
                    *(float2*)&An[264]     = make_float2(pa.y, pa.y);
                    *(float2*)&An[528]     = make_float2(pa.z, pa.z);
                    *(float2*)&An[792]     = make_float2(pa.w, pa.w);
                    __syncthreads();
                    buf ^= 1;
                }
            }
#pragma unroll
            for (int i = 0; i < 4; i++) {
                int gr = rowBase + ty * 4 + i;
                if (gr < n) {
                    float2 lo = unpack2(acc2[i][0]);
                    float2 hi = unpack2(acc2[i][1]);
                    *(float4*)&g_XW1[(size_t)gr * F_MID + tx * 4] =
                        make_float4(lo.x, lo.y, hi.x, hi.y);
                }
            }
        }
    }
    gbar();

    // ---- phase G: SPMM1 + relu  g_H = relu(Ahat @ g_XW1) ----
    {
        const float4* base = (const float4*)g_XW1;     // row stride 32 f4
        const int gw = bid * 32 + wid;
        for (int row = gw; row < n; row += NWARPS) {
            int s = g_rowptr[row];
            int e = g_rowptr[row + 1];
            float4 acc = make_float4(0.f, 0.f, 0.f, 0.f);
            int i = s;
            for (; i + 7 < e; i += 8) {
                float2 cw[8];
#pragma unroll
                for (int u = 0; u < 8; u++) cw[u] = __ldg(&g_cw[i + u]);
                float4 vv[8];
#pragma unroll
                for (int u = 0; u < 8; u++)
                    vv[u] = __ldg(&base[((unsigned)__float_as_int(cw[u].x) << 5) + lane]);
#pragma unroll
                for (int u = 0; u < 8; u++) {
                    acc.x += cw[u].y * vv[u].x;
                    acc.y += cw[u].y * vv[u].y;
                    acc.z += cw[u].y * vv[u].z;
                    acc.w += cw[u].y * vv[u].w;
                }
            }
            if (i + 3 < e) {
                float2 cw[4];
#pragma unroll
                for (int u = 0; u < 4; u++) cw[u] = __ldg(&g_cw[i + u]);
                float4 vv[4];
#pragma unroll
                for (int u = 0; u < 4; u++)
                    vv[u] = __ldg(&base[((unsigned)__float_as_int(cw[u].x) << 5) + lane]);
#pragma unroll
                for (int u = 0; u < 4; u++) {
                    acc.x += cw[u].y * vv[u].x;
                    acc.y += cw[u].y * vv[u].y;
                    acc.z += cw[u].y * vv[u].z;
                    acc.w += cw[u].y * vv[u].w;
                }
                i += 4;
            }
            for (; i < e; i++) {
                float2 cw = __ldg(&g_cw[i]);
                float4 vv = __ldg(&base[((unsigned)__float_as_int(cw.x) << 5) + lane]);
                acc.x += cw.y * vv.x; acc.y += cw.y * vv.y;
                acc.z += cw.y * vv.z; acc.w += cw.y * vv.w;
            }
            acc.x = fmaxf(acc.x, 0.f); acc.y = fmaxf(acc.y, 0.f);
            acc.z = fmaxf(acc.z, 0.f); acc.w = fmaxf(acc.w, 0.f);
            ((float4*)g_H)[(unsigned)row * 32u + lane] = acc;
        }
    }
    gbar();

    // ---- phase H: GEMM2  g_HW2[n,64] = g_H[n,128] @ W2[128,64] ----
    // W2 smem-resident; dup-A; BM=256, BK=32, TM=4, TN=4 (f32x2).
    {
        float* Ws = smp;                 // [128][64] = 8192 floats
        float* As = smp + 8192;          // 2 x [32][520] dup layout
        const int tx = tid & 15;         // *4 -> 64 cols
        const int ty = tid >> 4;         // *4 -> 256 rows
        const int ar = tid >> 3;         // A row base (0..127), +128 for second
        const int akv = tid & 7;
        const int tiles = (n + 255) >> 8;

        // load all of W2 once (2048 float4, 2 per thread)
        for (int i = tid; i < 8192 / 4; i += NTHR)
            ((float4*)Ws)[i] = ((const float4*)W2)[i];

        for (int tile = bid; tile < tiles; tile += NBLK) {
            const int rowBase = tile << 8;
            const int gr0 = rowBase + ar;
            const int gr1 = rowBase + ar + 128;
            unsigned long long acc2[4][2];
#pragma unroll
            for (int i = 0; i < 4; i++) { acc2[i][0] = 0ull; acc2[i][1] = 0ull; }

            float4 pa0 = make_float4(0.f, 0.f, 0.f, 0.f);
            float4 pa1 = make_float4(0.f, 0.f, 0.f, 0.f);
            if (gr0 < n) pa0 = *(const float4*)&g_H[(size_t)gr0 * F_MID + akv * 4];
            if (gr1 < n) pa1 = *(const float4*)&g_H[(size_t)gr1 * F_MID + akv * 4];
            __syncthreads();
            {
                float* A0 = As + (akv * 4) * 520 + 2 * ar;
                *(float2*)&A0[0]         = make_float2(pa0.x, pa0.x);
                *(float2*)&A0[520]       = make_float2(pa0.y, pa0.y);
                *(float2*)&A0[1040]      = make_float2(pa0.z, pa0.z);
                *(float2*)&A0[1560]      = make_float2(pa0.w, pa0.w);
                *(float2*)&A0[256]       = make_float2(pa1.x, pa1.x);
                *(float2*)&A0[520 + 256] = make_float2(pa1.y, pa1.y);
                *(float2*)&A0[1040 + 256]= make_float2(pa1.z, pa1.z);
                *(float2*)&A0[1560 + 256]= make_float2(pa1.w, pa1.w);
            }
            __syncthreads();

            int buf = 0;
#pragma unroll
            for (int k0 = 0; k0 < F_MID; k0 += 32) {
                if (k0 + 32 < F_MID) {
                    if (gr0 < n)
                        pa0 = *(const float4*)&g_H[(size_t)gr0 * F_MID + (k0 + 32) + akv * 4];
                    if (gr1 < n)
                        pa1 = *(const float4*)&g_H[(size_t)gr1 * F_MID + (k0 + 32) + akv * 4];
                }
                const float* Ab = As + buf * 16640;
#pragma unroll
                for (int k = 0; k < 32; k++) {
                    const unsigned long long* Ad =
                        (const unsigned long long*)&Ab[k * 520 + ty * 8];
                    unsigned long long a0 = Ad[0], a1 = Ad[1];
                    unsigned long long a2 = Ad[2], a3 = Ad[3];
                    const unsigned long long* rb =
                        (const unsigned long long*)&Ws[(k0 + k) * 64 + tx * 4];
                    unsigned long long b01 = rb[0], b23 = rb[1];
                    ffma2(acc2[0][0], a0, b01); ffma2(acc2[0][1], a0, b23);
                    ffma2(acc2[1][0], a1, b01); ffma2(acc2[1][1], a1, b23);
                    ffma2(acc2[2][0], a2, b01); ffma2(acc2[2][1], a2, b23);
                    ffma2(acc2[3][0], a3, b01); ffma2(acc2[3][1], a3, b23);
                }
                if (k0 + 32 < F_MID) {
                    float* An = As + (buf ^ 1) * 16640 + (akv * 4) * 520 + 2 * ar;
                    *(float2*)&An[0]         = make_float2(pa0.x, pa0.x);
                    *(float2*)&An[520]       = make_float2(pa0.y, pa0.y);
                    *(float2*)&An[1040]      = make_float2(pa0.z, pa0.z);
                    *(float2*)&An[1560]      = make_float2(pa0.w, pa0.w);
                    *(float2*)&An[256]       = make_float2(pa1.x, pa1.x);
                    *(float2*)&An[520 + 256] = make_float2(pa1.y, pa1.y);
                    *(float2*)&An[1040 + 256]= make_float2(pa1.z, pa1.z);
                    *(float2*)&An[1560 + 256]= make_float2(pa1.w, pa1.w);
                    __syncthreads();
                    buf ^= 1;
                }
            }
#pragma unroll
            for (int i = 0; i < 4; i++) {
                int gr = rowBase + ty * 4 + i;
                if (gr < n) {
                    float2 lo = unpack2(acc2[i][0]);
                    float2 hi = unpack2(acc2[i][1]);
                    *(float4*)&g_HW2[(size_t)gr * F_OUT + tx * 4] =
                        make_float4(lo.x, lo.y, hi.x, hi.y);
                }
            }
        }
    }
    gbar();

    // ---- phase I: SPMM2  out = Ahat @ g_HW2 ----
    {
        const float2* base = (const float2*)g_HW2;     // row stride 32 f2
        const int gw = bid * 32 + wid;
        for (int row = gw; row < n; row += NWARPS) {
            int s = g_rowptr[row];
            int e = g_rowptr[row + 1];
            float2 acc = make_float2(0.f, 0.f);
            int i = s;
            for (; i + 7 < e; i += 8) {
                float2 cw[8];
#pragma unroll
                for (int u = 0; u < 8; u++) cw[u] = __ldg(&g_cw[i + u]);
                float2 vv[8];
#pragma unroll
                for (int u = 0; u < 8; u++)
                    vv[u] = __ldg(&base[((unsigned)__float_as_int(cw[u].x) << 5) + lane]);
#pragma unroll
                for (int u = 0; u < 8; u++) {
                    acc.x += cw[u].y * vv[u].x;
                    acc.y += cw[u].y * vv[u].y;
                }
            }
            if (i + 3 < e) {
                float2 cw[4];
#pragma unroll
                for (int u = 0; u < 4; u++) cw[u] = __ldg(&g_cw[i + u]);
                float2 vv[4];
#pragma unroll
                for (int u = 0; u < 4; u++)
                    vv[u] = __ldg(&base[((unsigned)__float_as_int(cw[u].x) << 5) + lane]);
#pragma unroll
                for (int u = 0; u < 4; u++) {
                    acc.x += cw[u].y * vv[u].x;
                    acc.y += cw[u].y * vv[u].y;
                }
                i += 4;
            }
            for (; i < e; i++) {
                float2 cw = __ldg(&g_cw[i]);
                float2 vv = __ldg(&base[((unsigned)__float_as_int(cw.x) << 5) + lane]);
                acc.x += cw.y * vv.x;
                acc.y += cw.y * vv.y;
            }
            ((float2*)out)[(unsigned)row * 32u + lane] = acc;
        }
    }
}

// ---------------- launch: ONE kernel, dynamic smem ----------------
extern "C" void kernel_launch(void* const* d_in, const int* in_sizes, int n_in,
                              void* d_out, int out_size) {
    const float* X  = (const float*)d_in[0];
    const float* W1 = (const float*)d_in[1];
    const float* W2 = (const float*)d_in[2];
    const int* erow = (const int*)d_in[3];
    const int* ecol = (const int*)d_in[4];
    const int E = in_sizes[3];
    const int n = in_sizes[0] / F_IN;
    float* out = (float*)d_out;

    cudaFuncSetAttribute(k_gcn, cudaFuncAttributeMaxDynamicSharedMemorySize,
                         SMEM_BYTES);
    k_gcn<<<NBLK, NTHR, SMEM_BYTES>>>(X, W1, W2, erow, ecol, E, n, out);
}

// round 14
// speedup vs baseline: 1.3411x; 1.3411x over previous
#include <cuda_runtime.h>
#include <cuda_bf16.h>
#include <cstdint>

// ---------------- problem constants ----------------
#define MAX_N 100000
#define MAX_E 1700000
#define F_IN  256
#define F_MID 128
#define F_OUT 64
#define NBLK  148          // <= SM count; 1 CTA/SM -> co-residency guaranteed
#define NTHR  1024
#define NWARPS (NBLK * 32) // 4736 warps chip-wide

// dynamic smem: GEMM1 phase needs W1(32768) + 2 x A[32][260] (2*8320)
// = 49408 floats = 197632 bytes (< 227KB cap)
#define SMEM_FLOATS 49408
#define SMEM_BYTES  (SMEM_FLOATS * 4)

// ---------------- device scratch (no allocations allowed) ----------------
__device__ int    g_deg[MAX_N];
__device__ float  g_dis[MAX_N];
__device__ int    g_rowptr[MAX_N + 1];
__device__ int    g_cursor[MAX_N];
__device__ int    g_bsum[128];
__device__ volatile unsigned g_bar_gen;   // monotonic, NEVER reset (replay-safe)
__device__ unsigned g_bar_cnt;
__device__ float2 g_cw[MAX_E];
__device__ float  g_XW1[(size_t)MAX_N * F_MID];
__device__ float  g_H[(size_t)MAX_N * F_MID];
__device__ float  g_HW2[(size_t)MAX_N * F_OUT];

// ---------------- packed f32x2 helpers (sm_103a) ----------------
__device__ __forceinline__ unsigned long long pack2(float x, float y) {
    unsigned long long r;
    asm("mov.b64 %0, {%1, %2};" : "=l"(r) : "f"(x), "f"(y));
    return r;
}
__device__ __forceinline__ void ffma2(unsigned long long& d,
                                      unsigned long long a,
                                      unsigned long long b) {
    asm("fma.rn.f32x2 %0, %1, %2, %0;" : "+l"(d) : "l"(a), "l"(b));
}
__device__ __forceinline__ float2 unpack2(unsigned long long v) {
    float lo, hi;
    asm("mov.b64 {%0, %1}, %2;" : "=f"(lo), "=f"(hi) : "l"(v));
    return make_float2(lo, hi);
}

// ---------------- grid barrier (all NBLK blocks co-resident) ----------------
__device__ __forceinline__ void gbar() {
    __syncthreads();
    if (threadIdx.x == 0) {
        __threadfence();
        unsigned gen = g_bar_gen;                       // read BEFORE arrive
        if (atomicAdd(&g_bar_cnt, 1u) == NBLK - 1u) {
            g_bar_cnt = 0u;                             // reset BEFORE release
            __threadfence();
            g_bar_gen = gen + 1u;                       // release
        } else {
            while (g_bar_gen == gen) { }                // spin (volatile read)
        }
        __threadfence();
    }
    __syncthreads();
}

// ---------------- the whole GCN in one persistent kernel ----------------
__global__ __launch_bounds__(NTHR, 1)
void k_gcn(const float* __restrict__ X,  const float* __restrict__ W1,
           const float* __restrict__ W2, const int* __restrict__ erow,
           const int* __restrict__ ecol, int E, int n,
           float* __restrict__ out) {
    extern __shared__ float smp[];
    const int tid = threadIdx.x;
    const int bid = blockIdx.x;
    const int lane = tid & 31;
    const int wid  = tid >> 5;
    const int gstride = NBLK * NTHR;      // 151552

    // ---- phase A: zero degrees ----
    for (int i = bid * NTHR + tid; i < n; i += gstride) g_deg[i] = 0;
    gbar();

    // ---- phase B: degree histogram ----
    for (int e = bid * NTHR + tid; e < E; e += gstride)
        atomicAdd(&g_deg[erow[e]], 1);
    gbar();

    // ---- phase C: dis + block-local scan (blocks 0..97, 1024 rows each) ----
    int v = 0, incl = 0;
    const int i_scan = bid * NTHR + tid;
    if (bid < 98) {
        int* s = (int*)smp;
        v = (i_scan < n) ? g_deg[i_scan] : 0;
        if (i_scan < n) g_dis[i_scan] = rsqrtf((float)v);
        s[tid] = v;
        __syncthreads();
#pragma unroll
        for (int off = 1; off < NTHR; off <<= 1) {
            int t = (tid >= off) ? s[tid - off] : 0;
            __syncthreads();
            s[tid] += t;
            __syncthreads();
        }
        incl = s[tid];
        if (tid == NTHR - 1) g_bsum[bid] = incl;
    }
    gbar();

    // ---- phase D: block offset + rowptr/cursor ----
    if (bid < 98) {
        int* s2 = (int*)smp;
        if (tid < 128) s2[tid] = (tid < bid) ? g_bsum[tid] : 0;
        __syncthreads();
        if (tid < 64) s2[tid] += s2[tid + 64];
        __syncthreads();
        if (tid < 32) {
            int t = s2[tid] + s2[tid + 32];
#pragma unroll
            for (int off = 16; off > 0; off >>= 1)
                t += __shfl_down_sync(0xffffffffu, t, off);
            if (tid == 0) s2[0] = t;
        }
        __syncthreads();
        int excl = s2[0] + incl - v;
        if (i_scan < n) {
            g_rowptr[i_scan] = excl;
            g_cursor[i_scan] = excl;
            if (i_scan == n - 1) g_rowptr[n] = excl + v;
        }
    }
    gbar();

    // ---- phase E: scatter edges into CSR ----
    for (int e = bid * NTHR + tid; e < E; e += gstride) {
        int r = erow[e];
        int c = ecol[e];
        int p = atomicAdd(&g_cursor[r], 1);
        g_cw[p] = make_float2(__int_as_float(c), g_dis[r] * g_dis[c]);
    }
    gbar();

    // ---- phase F: GEMM1  g_XW1[n,128] = X[n,256] @ W1[256,128] ----
    // W1 smem-resident; A ping-pong w/ register prefetch.
    // BM=256, BK=32, TM=8, TN=4 (f32x2): halves B-smem bytes/MAC vs TM=4.
    {
        float* Ws = smp;                 // [256][128] = 32768 floats
        float* As = smp + 32768;         // 2 x [32][260] = 2 x 8320
        const int tx = lane;             // *4 -> 128 cols
        const int ty = wid;              // *8 -> 256 rows
        const int ar = tid >> 3;         // A fill row (0..127), +128 for 2nd
        const int akv = tid & 7;         // A k-vec (0..7)
        const int tiles = (n + 255) >> 8;

        // load all of W1 once (8192 float4, 8 per thread)
        for (int i = tid; i < 32768 / 4; i += NTHR)
            ((float4*)Ws)[i] = ((const float4*)W1)[i];

        for (int tile = bid; tile < tiles; tile += NBLK) {
            const int rowBase = tile << 8;
            const int gr0 = rowBase + ar;
            const int gr1 = rowBase + ar + 128;
            unsigned long long acc2[8][2];
#pragma unroll
            for (int i = 0; i < 8; i++) { acc2[i][0] = 0ull; acc2[i][1] = 0ull; }

            float4 pa0 = make_float4(0.f, 0.f, 0.f, 0.f);
            float4 pa1 = make_float4(0.f, 0.f, 0.f, 0.f);
            if (gr0 < n) pa0 = *(const float4*)&X[(size_t)gr0 * F_IN + akv * 4];
            if (gr1 < n) pa1 = *(const float4*)&X[(size_t)gr1 * F_IN + akv * 4];
            __syncthreads();    // protects prev tile's buffers + W1 load
            {
                float* A0 = As + (akv * 4) * 260 + ar;
                A0[0]         = pa0.x;  A0[260]       = pa0.y;
                A0[520]       = pa0.z;  A0[780]       = pa0.w;
                A0[128]       = pa1.x;  A0[260 + 128] = pa1.y;
                A0[520 + 128] = pa1.z;  A0[780 + 128] = pa1.w;
            }
            __syncthreads();

            int buf = 0;
#pragma unroll
            for (int k0 = 0; k0 < F_IN; k0 += 32) {
                if (k0 + 32 < F_IN) {
                    if (gr0 < n)
                        pa0 = *(const float4*)&X[(size_t)gr0 * F_IN + (k0 + 32) + akv * 4];
                    if (gr1 < n)
                        pa1 = *(const float4*)&X[(size_t)gr1 * F_IN + (k0 + 32) + akv * 4];
                }
                const float* Ab = As + buf * 8320;
#pragma unroll
                for (int k = 0; k < 32; k++) {
                    float4 ra0 = *(const float4*)&Ab[k * 260 + ty * 8];
                    float4 ra1 = *(const float4*)&Ab[k * 260 + ty * 8 + 4];
                    const unsigned long long* rb =
                        (const unsigned long long*)&Ws[(k0 + k) * 128 + tx * 4];
                    unsigned long long b01 = rb[0], b23 = rb[1];
                    unsigned long long a;
                    a = pack2(ra0.x, ra0.x); ffma2(acc2[0][0], a, b01); ffma2(acc2[0][1], a, b23);
                    a = pack2(ra0.y, ra0.y); ffma2(acc2[1][0], a, b01); ffma2(acc2[1][1], a, b23);
                    a = pack2(ra0.z, ra0.z); ffma2(acc2[2][0], a, b01); ffma2(acc2[2][1], a, b23);
                    a = pack2(ra0.w, ra0.w); ffma2(acc2[3][0], a, b01); ffma2(acc2[3][1], a, b23);
                    a = pack2(ra1.x, ra1.x); ffma2(acc2[4][0], a, b01); ffma2(acc2[4][1], a, b23);
                    a = pack2(ra1.y, ra1.y); ffma2(acc2[5][0], a, b01); ffma2(acc2[5][1], a, b23);
                    a = pack2(ra1.z, ra1.z); ffma2(acc2[6][0], a, b01); ffma2(acc2[6][1], a, b23);
                    a = pack2(ra1.w, ra1.w); ffma2(acc2[7][0], a, b01); ffma2(acc2[7][1], a, b23);
                }
                if (k0 + 32 < F_IN) {
                    float* An = As + (buf ^ 1) * 8320 + (akv * 4) * 260 + ar;
                    An[0]         = pa0.x;  An[260]       = pa0.y;
                    An[520]       = pa0.z;  An[780]       = pa0.w;
                    An[128]       = pa1.x;  An[260 + 128] = pa1.y;
                    An[520 + 128] = pa1.z;  An[780 + 128] = pa1.w;
                    __syncthreads();
                    buf ^= 1;
                }
            }
#pragma unroll
            for (int i = 0; i < 8; i++) {
                int gr = rowBase + ty * 8 + i;
                if (gr < n) {
                    float2 lo = unpack2(acc2[i][0]);
                    float2 hi = unpack2(acc2[i][1]);
                    *(float4*)&g_XW1[(size_t)gr * F_MID + tx * 4] =
                        make_float4(lo.x, lo.y, hi.x, hi.y);
                }
            }
        }
    }
    gbar();

    // ---- phase G: SPMM1 + relu  g_H = relu(Ahat @ g_XW1) ----
    {
        const float4* base = (const float4*)g_XW1;     // row stride 32 f4
        const int gw = bid * 32 + wid;
        for (int row = gw; row < n; row += NWARPS) {
            int s = g_rowptr[row];
            int e = g_rowptr[row + 1];
            float4 acc = make_float4(0.f, 0.f, 0.f, 0.f);
            int i = s;
            for (; i + 7 < e; i += 8) {
                float2 cw[8];
#pragma unroll
                for (int u = 0; u < 8; u++) cw[u] = __ldg(&g_cw[i + u]);
                float4 vv[8];
#pragma unroll
                for (int u = 0; u < 8; u++)
                    vv[u] = __ldg(&base[((unsigned)__float_as_int(cw[u].x) << 5) + lane]);
#pragma unroll
                for (int u = 0; u < 8; u++) {
                    acc.x += cw[u].y * vv[u].x;
                    acc.y += cw[u].y * vv[u].y;
                    acc.z += cw[u].y * vv[u].z;
                    acc.w += cw[u].y * vv[u].w;
                }
            }
            if (i + 3 < e) {
                float2 cw[4];
#pragma unroll
                for (int u = 0; u < 4; u++) cw[u] = __ldg(&g_cw[i + u]);
                float4 vv[4];
#pragma unroll
                for (int u = 0; u < 4; u++)
                    vv[u] = __ldg(&base[((unsigned)__float_as_int(cw[u].x) << 5) + lane]);
#pragma unroll
                for (int u = 0; u < 4; u++) {
                    acc.x += cw[u].y * vv[u].x;
                    acc.y += cw[u].y * vv[u].y;
                    acc.z += cw[u].y * vv[u].z;
                    acc.w += cw[u].y * vv[u].w;
                }
                i += 4;
            }
            for (; i < e; i++) {
                float2 cw = __ldg(&g_cw[i]);
                float4 vv = __ldg(&base[((unsigned)__float_as_int(cw.x) << 5) + lane]);
                acc.x += cw.y * vv.x; acc.y += cw.y * vv.y;
                acc.z += cw.y * vv.z; acc.w += cw.y * vv.w;
            }
            acc.x = fmaxf(acc.x, 0.f); acc.y = fmaxf(acc.y, 0.f);
            acc.z = fmaxf(acc.z, 0.f); acc.w = fmaxf(acc.w, 0.f);
            ((float4*)g_H)[(unsigned)row * 32u + lane] = acc;
        }
    }
    gbar();

    // ---- phase H: GEMM2  g_HW2[n,64] = g_H[n,128] @ W2[128,64] ----
    // W2 smem-resident; ping-pong prefetch; BM=256, BK=32, TM=4, TN=4.
    {
        float* Ws = smp;                 // [128][64] = 8192 floats
        float* As = smp + 8192;          // 2 x [32][260] = 2 x 8320
        const int tx = tid & 15;         // *4 -> 64 cols
        const int ty = tid >> 4;         // *4 -> 256 rows
        const int ar = tid >> 3;         // A fill row (0..127), +128 for 2nd
        const int akv = tid & 7;
        const int tiles = (n + 255) >> 8;

        // load all of W2 once (2048 float4, 2 per thread)
        for (int i = tid; i < 8192 / 4; i += NTHR)
            ((float4*)Ws)[i] = ((const float4*)W2)[i];

        for (int tile = bid; tile < tiles; tile += NBLK) {
            const int rowBase = tile << 8;
            const int gr0 = rowBase + ar;
            const int gr1 = rowBase + ar + 128;
            unsigned long long acc2[4][2];
#pragma unroll
            for (int i = 0; i < 4; i++) { acc2[i][0] = 0ull; acc2[i][1] = 0ull; }

            float4 pa0 = make_float4(0.f, 0.f, 0.f, 0.f);
            float4 pa1 = make_float4(0.f, 0.f, 0.f, 0.f);
            if (gr0 < n) pa0 = *(const float4*)&g_H[(size_t)gr0 * F_MID + akv * 4];
            if (gr1 < n) pa1 = *(const float4*)&g_H[(size_t)gr1 * F_MID + akv * 4];
            __syncthreads();
            {
                float* A0 = As + (akv * 4) * 260 + ar;
                A0[0]         = pa0.x;  A0[260]       = pa0.y;
                A0[520]       = pa0.z;  A0[780]       = pa0.w;
                A0[128]       = pa1.x;  A0[260 + 128] = pa1.y;
                A0[520 + 128] = pa1.z;  A0[780 + 128] = pa1.w;
            }
            __syncthreads();

            int buf = 0;
#pragma unroll
            for (int k0 = 0; k0 < F_MID; k0 += 32) {
                if (k0 + 32 < F_MID) {
                    if (gr0 < n)
                        pa0 = *(const float4*)&g_H[(size_t)gr0 * F_MID + (k0 + 32) + akv * 4];
                    if (gr1 < n)
                        pa1 = *(const float4*)&g_H[(size_t)gr1 * F_MID + (k0 + 32) + akv * 4];
                }
                const float* Ab = As + buf * 8320;
#pragma unroll
                for (int k = 0; k < 32; k++) {
                    float4 ra = *(const float4*)&Ab[k * 260 + ty * 4];
                    const unsigned long long* rb =
                        (const unsigned long long*)&Ws[(k0 + k) * 64 + tx * 4];
                    unsigned long long b01 = rb[0], b23 = rb[1];
                    unsigned long long a;
                    a = pack2(ra.x, ra.x); ffma2(acc2[0][0], a, b01); ffma2(acc2[0][1], a, b23);
                    a = pack2(ra.y, ra.y); ffma2(acc2[1][0], a, b01); ffma2(acc2[1][1], a, b23);
                    a = pack2(ra.z, ra.z); ffma2(acc2[2][0], a, b01); ffma2(acc2[2][1], a, b23);
                    a = pack2(ra.w, ra.w); ffma2(acc2[3][0], a, b01); ffma2(acc2[3][1], a, b23);
                }
                if (k0 + 32 < F_MID) {
                    float* An = As + (buf ^ 1) * 8320 + (akv * 4) * 260 + ar;
                    An[0]         = pa0.x;  An[260]       = pa0.y;
                    An[520]       = pa0.z;  An[780]       = pa0.w;
                    An[128]       = pa1.x;  An[260 + 128] = pa1.y;
                    An[520 + 128] = pa1.z;  An[780 + 128] = pa1.w;
                    __syncthreads();
                    buf ^= 1;
                }
            }
#pragma unroll
            for (int i = 0; i < 4; i++) {
                int gr = rowBase + ty * 4 + i;
                if (gr < n) {
                    float2 lo = unpack2(acc2[i][0]);
                    float2 hi = unpack2(acc2[i][1]);
                    *(float4*)&g_HW2[(size_t)gr * F_OUT + tx * 4] =
                        make_float4(lo.x, lo.y, hi.x, hi.y);
                }
            }
        }
    }
    gbar();

    // ---- phase I: SPMM2  out = Ahat @ g_HW2 ----
    {
        const float2* base = (const float2*)g_HW2;     // row stride 32 f2
        const int gw = bid * 32 + wid;
        for (int row = gw; row < n; row += NWARPS) {
            int s = g_rowptr[row];
            int e = g_rowptr[row + 1];
            float2 acc = make_float2(0.f, 0.f);
            int i = s;
            for (; i + 7 < e; i += 8) {
                float2 cw[8];
#pragma unroll
                for (int u = 0; u < 8; u++) cw[u] = __ldg(&g_cw[i + u]);
                float2 vv[8];
#pragma unroll
                for (int u = 0; u < 8; u++)
                    vv[u] = __ldg(&base[((unsigned)__float_as_int(cw[u].x) << 5) + lane]);
#pragma unroll
                for (int u = 0; u < 8; u++) {
                    acc.x += cw[u].y * vv[u].x;
                    acc.y += cw[u].y * vv[u].y;
                }
            }
            if (i + 3 < e) {
                float2 cw[4];
#pragma unroll
                for (int u = 0; u < 4; u++) cw[u] = __ldg(&g_cw[i + u]);
                float2 vv[4];
#pragma unroll
                for (int u = 0; u < 4; u++)
                    vv[u] = __ldg(&base[((unsigned)__float_as_int(cw[u].x) << 5) + lane]);
#pragma unroll
                for (int u = 0; u < 4; u++) {
                    acc.x += cw[u].y * vv[u].x;
                    acc.y += cw[u].y * vv[u].y;
                }
                i += 4;
            }
            for (; i < e; i++) {
                float2 cw = __ldg(&g_cw[i]);
                float2 vv = __ldg(&base[((unsigned)__float_as_int(cw.x) << 5) + lane]);
                acc.x += cw.y * vv.x;
                acc.y += cw.y * vv.y;
            }
            ((float2*)out)[(unsigned)row * 32u + lane] = acc;
        }
    }
}

// ---------------- launch: ONE kernel, dynamic smem ----------------
extern "C" void kernel_launch(void* const* d_in, const int* in_sizes, int n_in,
                              void* d_out, int out_size) {
    const float* X  = (const float*)d_in[0];
    const float* W1 = (const float*)d_in[1];
    const float* W2 = (const float*)d_in[2];
    const int* erow = (const int*)d_in[3];
    const int* ecol = (const int*)d_in[4];
    const int E = in_sizes[3];
    const int n = in_sizes[0] / F_IN;
    float* out = (float*)d_out;

    cudaFuncSetAttribute(k_gcn, cudaFuncAttributeMaxDynamicSharedMemorySize,
                         SMEM_BYTES);
    k_gcn<<<NBLK, NTHR, SMEM_BYTES>>>(X, W1, W2, erow, ecol, E, n, out);
}